// round 2
// baseline (speedup 1.0000x reference)
#include <cuda_runtime.h>
#include <math.h>

#define BLOCK 256

// Scratch for per-block partial sums (num, den). Fully overwritten each launch.
__device__ float2 g_partials[128];

__device__ __forceinline__ float cross2f(float ax, float ay, float bx, float by) {
    return ax * by - ay * bx;
}

// BEV intersection area of two rotated rectangles, replicating the JAX
// reference algorithm (candidate points -> centroid -> stable angle sort ->
// shoelace with pts[0] padding).
__device__ float pair_bev_inter(const float a[7], const float b[7]) {
    // ---- exact quick reject: if bounding circles are separated, the
    // reference produces zero valid candidate points -> area exactly 0.
    {
        float dx = a[0] - b[0], dy = a[1] - b[1];
        float ra = 0.5f * sqrtf(a[3] * a[3] + a[4] * a[4]);
        float rb = 0.5f * sqrtf(b[3] * b[3] + b[4] * b[4]);
        float rr = ra + rb + 1e-3f;  // margin >> 1e-5 tolerance in reference
        if (dx * dx + dy * dy > rr * rr) return 0.0f;
    }

    const float CTX[4] = {0.5f, -0.5f, -0.5f, 0.5f};
    const float CTY[4] = {0.5f, 0.5f, -0.5f, -0.5f};

    float ac = cosf(a[6]), as = sinf(a[6]);
    float bc = cosf(b[6]), bs = sinf(b[6]);

    float cax[4], cay[4], cbx[4], cby[4];
#pragma unroll
    for (int i = 0; i < 4; i++) {
        float lx = CTX[i] * a[3], ly = CTY[i] * a[4];
        cax[i] = lx * ac - ly * as + a[0];
        cay[i] = lx * as + ly * ac + a[1];
        lx = CTX[i] * b[3]; ly = CTY[i] * b[4];
        cbx[i] = lx * bc - ly * bs + b[0];
        cby[i] = lx * bs + ly * bc + b[1];
    }

    float candx[24], candy[24];
    bool valid[24];

    // corners of A tested against box B
#pragma unroll
    for (int i = 0; i < 4; i++) {
        candx[i] = cax[i]; candy[i] = cay[i];
        float dx = cax[i] - b[0], dy = cay[i] - b[1];
        float qx = dx * bc + dy * bs;
        float qy = -dx * bs + dy * bc;
        valid[i] = (fabsf(qx) <= b[3] * 0.5f + 1e-5f) &&
                   (fabsf(qy) <= b[4] * 0.5f + 1e-5f);
    }
    // corners of B tested against box A
#pragma unroll
    for (int i = 0; i < 4; i++) {
        candx[4 + i] = cbx[i]; candy[4 + i] = cby[i];
        float dx = cbx[i] - a[0], dy = cby[i] - a[1];
        float qx = dx * ac + dy * as;
        float qy = -dx * as + dy * ac;
        valid[4 + i] = (fabsf(qx) <= a[3] * 0.5f + 1e-5f) &&
                       (fabsf(qy) <= a[4] * 0.5f + 1e-5f);
    }
    // 16 edge-edge intersections
#pragma unroll
    for (int i = 0; i < 4; i++) {
        float p1x = cax[i], p1y = cay[i];
        float p2x = cax[(i + 1) & 3], p2y = cay[(i + 1) & 3];
        float d1x = p2x - p1x, d1y = p2y - p1y;
#pragma unroll
        for (int j = 0; j < 4; j++) {
            float q1x = cbx[j], q1y = cby[j];
            float q2x = cbx[(j + 1) & 3], q2y = cby[(j + 1) & 3];
            float d2x = q2x - q1x, d2y = q2y - q1y;
            float rx = q1x - p1x, ry = q1y - p1y;
            float den = cross2f(d1x, d1y, d2x, d2y);
            float safe = (fabsf(den) > 1e-8f) ? den : 1.0f;
            float t = cross2f(rx, ry, d2x, d2y) / safe;
            float u = cross2f(rx, ry, d1x, d1y) / safe;
            bool iv = (fabsf(den) > 1e-8f) &&
                      (t >= -1e-6f) && (t <= 1.0f + 1e-6f) &&
                      (u >= -1e-6f) && (u <= 1.0f + 1e-6f);
            int k = 8 + i * 4 + j;
            candx[k] = p1x + t * d1x;
            candy[k] = p1y + t * d1y;
            valid[k] = iv;
        }
    }

    // centroid of valid points
    float n = 0.0f, sx = 0.0f, sy = 0.0f;
#pragma unroll
    for (int k = 0; k < 24; k++) {
        if (valid[k]) { n += 1.0f; sx += candx[k]; sy += candy[k]; }
    }
    float inv = 1.0f / fmaxf(n, 1.0f);
    float cenx = sx * inv, ceny = sy * inv;

    // angles: invalid -> 1e9 (sorts to end, stable)
    float ang[24];
#pragma unroll
    for (int k = 0; k < 24; k++) {
        ang[k] = valid[k] ? atan2f(candy[k] - ceny, candx[k] - cenx) : 1e9f;
    }

    // stable insertion argsort by angle (matches jnp.argsort stability)
    int order[24];
#pragma unroll
    for (int k = 0; k < 24; k++) order[k] = k;
    for (int k = 1; k < 24; k++) {
        int o = order[k];
        float av = ang[o];
        int m = k - 1;
        while (m >= 0 && ang[order[m]] > av) {
            order[m + 1] = order[m];
            m--;
        }
        order[m + 1] = o;
    }

    // sorted points, invalid padded with pts[0]
    int o0 = order[0];
    float p0x = candx[o0], p0y = candy[o0];
    float px[24], py[24];
    for (int k = 0; k < 24; k++) {
        int o = order[k];
        if (valid[o]) { px[k] = candx[o]; py[k] = candy[o]; }
        else          { px[k] = p0x;      py[k] = p0y; }
    }

    // shoelace over 24 (padded duplicates contribute 0)
    float s = 0.0f;
    for (int k = 0; k < 24; k++) {
        int k2 = (k + 1) % 24;
        s += px[k] * py[k2] - py[k] * px[k2];
    }
    float area = 0.5f * fabsf(s);
    return (n >= 3.0f) ? area : 0.0f;
}

__global__ void iou_loss_main(const float* __restrict__ iou_pred,
                              const int* __restrict__ mask,
                              const int* __restrict__ ind,
                              const float* __restrict__ box_pred,
                              const float* __restrict__ box_gt,
                              int M, int HW, int total)
{
    int tid = blockIdx.x * BLOCK + threadIdx.x;
    float num = 0.0f, den = 0.0f;
    if (tid < total) {
        int b = tid / M;
        int idx = ind[tid];

        float pred = iou_pred[(size_t)b * HW + idx];

        float pb[7], gb[7];
        const float* bp = box_pred + (size_t)b * 7 * HW + idx;
#pragma unroll
        for (int d = 0; d < 7; d++) pb[d] = bp[(size_t)d * HW];
        const float* gp = box_gt + (size_t)tid * 7;
#pragma unroll
        for (int d = 0; d < 7; d++) gb[d] = gp[d];

        float inter_bev = pair_bev_inter(pb, gb);
        float top = fminf(pb[2] + pb[5] * 0.5f, gb[2] + gb[5] * 0.5f);
        float bot = fmaxf(pb[2] - pb[5] * 0.5f, gb[2] - gb[5] * 0.5f);
        float inter = inter_bev * fmaxf(top - bot, 0.0f);
        float va = pb[3] * pb[4] * pb[5];
        float vb = gb[3] * gb[4] * gb[5];
        float iou = inter / fmaxf(va + vb - inter, 1e-6f);
        float target = 2.0f * iou - 1.0f;

        float mm = (float)mask[tid];
        num = fabsf(pred - target) * mm;
        den = mm;
    }

    __shared__ float sn[BLOCK];
    __shared__ float sd[BLOCK];
    sn[threadIdx.x] = num;
    sd[threadIdx.x] = den;
    __syncthreads();
#pragma unroll
    for (int s = BLOCK / 2; s > 0; s >>= 1) {
        if (threadIdx.x < s) {
            sn[threadIdx.x] += sn[threadIdx.x + s];
            sd[threadIdx.x] += sd[threadIdx.x + s];
        }
        __syncthreads();
    }
    if (threadIdx.x == 0) {
        g_partials[blockIdx.x] = make_float2(sn[0], sd[0]);
    }
}

__global__ void iou_loss_final(float* __restrict__ out, int nblocks, int out_size)
{
    if (threadIdx.x == 0) {
        float num = 0.0f, den = 0.0f;
        for (int i = 0; i < nblocks; i++) {
            float2 p = g_partials[i];
            num += p.x;
            den += p.y;
        }
        float loss = num / (den + 1e-4f);
        for (int i = 0; i < out_size; i++) out[i] = loss;
    }
}

extern "C" void kernel_launch(void* const* d_in, const int* in_sizes, int n_in,
                              void* d_out, int out_size)
{
    const float* iou_pred = (const float*)d_in[0];  // (B,1,H,W)
    const int*   mask     = (const int*)d_in[1];    // (B,M)
    const int*   ind      = (const int*)d_in[2];    // (B,M)
    const float* box_pred = (const float*)d_in[3];  // (B,7,H,W)
    const float* box_gt   = (const float*)d_in[4];  // (B,M,7)

    const int B = 16;                  // fixed by problem setup
    int BM = in_sizes[1];              // B*M
    int M = BM / B;
    int HW = in_sizes[0] / B;          // C == 1

    int total = BM;
    int nblocks = (total + BLOCK - 1) / BLOCK;
    if (nblocks > 128) nblocks = 128;  // scratch bound (never hit: 8000/256=32)

    iou_loss_main<<<nblocks, BLOCK>>>(iou_pred, mask, ind, box_pred, box_gt,
                                      M, HW, total);
    iou_loss_final<<<1, 32>>>((float*)d_out, nblocks, out_size);
}

// round 3
// speedup vs baseline: 1.5320x; 1.5320x over previous
#include <cuda_runtime.h>
#include <math.h>

#define BLOCK 64
#define MAXBLOCKS 256

// Scratch: per-block partials + completion counter. Counter is reset to 0 by
// the last block every launch, so graph replays are deterministic.
__device__ float2 g_partials[MAXBLOCKS];
__device__ unsigned int g_count = 0;

__device__ __forceinline__ float cross2f(float ax, float ay, float bx, float by) {
    return ax * by - ay * bx;
}

// BEV intersection area of two rotated rectangles. Exactly replicates the JAX
// reference: candidate points -> centroid of valid -> stable angle sort ->
// shoelace. We compact valid points first; padding with pts[0] in the
// reference contributes zero area, so sorting only the valid set is identical.
__device__ float pair_bev_inter(const float a[7], const float b[7]) {
    // exact quick reject: separated bounding circles -> zero valid candidates
    {
        float dx = a[0] - b[0], dy = a[1] - b[1];
        float ra = 0.5f * sqrtf(a[3] * a[3] + a[4] * a[4]);
        float rb = 0.5f * sqrtf(b[3] * b[3] + b[4] * b[4]);
        float rr = ra + rb + 1e-3f;
        if (dx * dx + dy * dy > rr * rr) return 0.0f;
    }

    const float CTX[4] = {0.5f, -0.5f, -0.5f, 0.5f};
    const float CTY[4] = {0.5f, 0.5f, -0.5f, -0.5f};

    float ac = cosf(a[6]), as = sinf(a[6]);
    float bc = cosf(b[6]), bs = sinf(b[6]);

    float cax[4], cay[4], cbx[4], cby[4];
#pragma unroll
    for (int i = 0; i < 4; i++) {
        float lx = CTX[i] * a[3], ly = CTY[i] * a[4];
        cax[i] = lx * ac - ly * as + a[0];
        cay[i] = lx * as + ly * ac + a[1];
        lx = CTX[i] * b[3]; ly = CTY[i] * b[4];
        cbx[i] = lx * bc - ly * bs + b[0];
        cby[i] = lx * bs + ly * bc + b[1];
    }

    // compact valid candidates in reference order (A corners, B corners,
    // 16 edge intersections) -- preserves jnp.argsort stability.
    float vx[24], vy[24];
    int n = 0;
    float sx = 0.0f, sy = 0.0f;

#pragma unroll
    for (int i = 0; i < 4; i++) {
        float dx = cax[i] - b[0], dy = cay[i] - b[1];
        float qx = dx * bc + dy * bs;
        float qy = -dx * bs + dy * bc;
        if ((fabsf(qx) <= b[3] * 0.5f + 1e-5f) &&
            (fabsf(qy) <= b[4] * 0.5f + 1e-5f)) {
            vx[n] = cax[i]; vy[n] = cay[i];
            sx += cax[i]; sy += cay[i]; n++;
        }
    }
#pragma unroll
    for (int i = 0; i < 4; i++) {
        float dx = cbx[i] - a[0], dy = cby[i] - a[1];
        float qx = dx * ac + dy * as;
        float qy = -dx * as + dy * ac;
        if ((fabsf(qx) <= a[3] * 0.5f + 1e-5f) &&
            (fabsf(qy) <= a[4] * 0.5f + 1e-5f)) {
            vx[n] = cbx[i]; vy[n] = cby[i];
            sx += cbx[i]; sy += cby[i]; n++;
        }
    }
#pragma unroll
    for (int i = 0; i < 4; i++) {
        float p1x = cax[i], p1y = cay[i];
        float d1x = cax[(i + 1) & 3] - p1x, d1y = cay[(i + 1) & 3] - p1y;
#pragma unroll
        for (int j = 0; j < 4; j++) {
            float q1x = cbx[j], q1y = cby[j];
            float d2x = cbx[(j + 1) & 3] - q1x, d2y = cby[(j + 1) & 3] - q1y;
            float rx = q1x - p1x, ry = q1y - p1y;
            float den = cross2f(d1x, d1y, d2x, d2y);
            if (fabsf(den) > 1e-8f) {
                float t = cross2f(rx, ry, d2x, d2y) / den;
                float u = cross2f(rx, ry, d1x, d1y) / den;
                if ((t >= -1e-6f) && (t <= 1.0f + 1e-6f) &&
                    (u >= -1e-6f) && (u <= 1.0f + 1e-6f)) {
                    float ix = p1x + t * d1x, iy = p1y + t * d1y;
                    vx[n] = ix; vy[n] = iy;
                    sx += ix; sy += iy; n++;
                }
            }
        }
    }

    if (n < 3) return 0.0f;

    float inv = 1.0f / (float)n;
    float cenx = sx * inv, ceny = sy * inv;

    // stable insertion sort of (ang, vx, vy) by angle
    float ang[24];
    for (int k = 0; k < n; k++)
        ang[k] = atan2f(vy[k] - ceny, vx[k] - cenx);

    for (int k = 1; k < n; k++) {
        float av = ang[k], axv = vx[k], ayv = vy[k];
        int m = k - 1;
        while (m >= 0 && ang[m] > av) {
            ang[m + 1] = ang[m]; vx[m + 1] = vx[m]; vy[m + 1] = vy[m];
            m--;
        }
        ang[m + 1] = av; vx[m + 1] = axv; vy[m + 1] = ayv;
    }

    // shoelace over the n sorted points (closed polygon)
    float s = 0.0f;
    for (int k = 0; k < n; k++) {
        int k2 = (k + 1 == n) ? 0 : k + 1;
        s += vx[k] * vy[k2] - vy[k] * vx[k2];
    }
    return 0.5f * fabsf(s);
}

__global__ void iou_loss_fused(const float* __restrict__ iou_pred,
                               const int* __restrict__ mask,
                               const int* __restrict__ ind,
                               const float* __restrict__ box_pred,
                               const float* __restrict__ box_gt,
                               int M, int HW, int total,
                               float* __restrict__ out, int out_size)
{
    int tid = blockIdx.x * BLOCK + threadIdx.x;
    float num = 0.0f, den = 0.0f;
    if (tid < total) {
        int b = tid / M;
        int idx = ind[tid];

        float pred = iou_pred[(size_t)b * HW + idx];

        float pb[7], gb[7];
        const float* bp = box_pred + (size_t)b * 7 * HW + idx;
#pragma unroll
        for (int d = 0; d < 7; d++) pb[d] = bp[(size_t)d * HW];
        const float* gp = box_gt + (size_t)tid * 7;
#pragma unroll
        for (int d = 0; d < 7; d++) gb[d] = gp[d];

        float inter_bev = pair_bev_inter(pb, gb);
        float top = fminf(pb[2] + pb[5] * 0.5f, gb[2] + gb[5] * 0.5f);
        float bot = fmaxf(pb[2] - pb[5] * 0.5f, gb[2] - gb[5] * 0.5f);
        float inter = inter_bev * fmaxf(top - bot, 0.0f);
        float va = pb[3] * pb[4] * pb[5];
        float vb = gb[3] * gb[4] * gb[5];
        float iou = inter / fmaxf(va + vb - inter, 1e-6f);
        float target = 2.0f * iou - 1.0f;

        float mm = (float)mask[tid];
        num = fabsf(pred - target) * mm;
        den = mm;
    }

    // warp reduce
#pragma unroll
    for (int off = 16; off > 0; off >>= 1) {
        num += __shfl_down_sync(0xffffffffu, num, off);
        den += __shfl_down_sync(0xffffffffu, den, off);
    }
    __shared__ float2 swarp[BLOCK / 32];
    __shared__ bool s_last;
    int lane = threadIdx.x & 31, wid = threadIdx.x >> 5;
    if (lane == 0) swarp[wid] = make_float2(num, den);
    __syncthreads();

    if (threadIdx.x == 0) {
        float2 acc = swarp[0];
#pragma unroll
        for (int w = 1; w < BLOCK / 32; w++) {
            acc.x += swarp[w].x; acc.y += swarp[w].y;
        }
        g_partials[blockIdx.x] = acc;
        __threadfence();
        unsigned int v = atomicAdd(&g_count, 1u);
        s_last = (v == gridDim.x - 1);
    }
    __syncthreads();

    // last block to finish reduces all partials and writes the output
    if (s_last) {
        float pn = 0.0f, pd = 0.0f;
        for (int i = threadIdx.x; i < (int)gridDim.x; i += BLOCK) {
            float2 p = g_partials[i];
            pn += p.x; pd += p.y;
        }
#pragma unroll
        for (int off = 16; off > 0; off >>= 1) {
            pn += __shfl_down_sync(0xffffffffu, pn, off);
            pd += __shfl_down_sync(0xffffffffu, pd, off);
        }
        if (lane == 0) swarp[wid] = make_float2(pn, pd);
        __syncthreads();
        if (threadIdx.x == 0) {
            float2 acc = swarp[0];
#pragma unroll
            for (int w = 1; w < BLOCK / 32; w++) {
                acc.x += swarp[w].x; acc.y += swarp[w].y;
            }
            float loss = acc.x / (acc.y + 1e-4f);
            for (int i = 0; i < out_size; i++) out[i] = loss;
            g_count = 0;  // reset for next graph replay
        }
    }
}

extern "C" void kernel_launch(void* const* d_in, const int* in_sizes, int n_in,
                              void* d_out, int out_size)
{
    const float* iou_pred = (const float*)d_in[0];  // (B,1,H,W)
    const int*   mask     = (const int*)d_in[1];    // (B,M)
    const int*   ind      = (const int*)d_in[2];    // (B,M)
    const float* box_pred = (const float*)d_in[3];  // (B,7,H,W)
    const float* box_gt   = (const float*)d_in[4];  // (B,M,7)

    const int B = 16;
    int BM = in_sizes[1];     // B*M
    int M = BM / B;
    int HW = in_sizes[0] / B; // C == 1

    int total = BM;
    int nblocks = (total + BLOCK - 1) / BLOCK;
    if (nblocks > MAXBLOCKS) nblocks = MAXBLOCKS;  // 8000/64 = 125, never hit

    iou_loss_fused<<<nblocks, BLOCK>>>(iou_pred, mask, ind, box_pred, box_gt,
                                       M, HW, total, (float*)d_out, out_size);
}